// round 13
// baseline (speedup 1.0000x reference)
#include <cuda_runtime.h>
#include <cstdint>

// ---------------------------------------------------------------------------
// N=100000, 512 -> 16 -> 40, E=3.2M int32 edges.
// out = log_softmax( segsum(relu(segsum((xW1)[src])+b1)[src]) @ W2 + b2 )
// (W2 hoisted past the scatter by linearity of segment_sum.)
//
// R13 gemm1: warp=16 rows, lane=(rg,kg); chunk=32k (one 128B line/row);
// stage-load (r4,f8) -> line-amplification 1; smem tile stride 40 floats
// (STS/LDS.128 conflict-free); register double-buffer prefetch breaks the
// LDG convoy. W-broadcast amortized over 16 rows. FFMA2 col-pairs (proven).
// RULE: __device__ globals only referenced in device code (ATS trap).
// ---------------------------------------------------------------------------

#define NNODES 100000
#define HID 16
#define NEDGES 3200000
#define NB_SCAN 391         // ceil(NNODES/256)

__device__ __align__(16) float g_h1  [NNODES * HID];
__device__ __align__(16) float g_agg1[NNODES * HID];
__device__ __align__(16) float g_agg2[NNODES * HID];
__device__ int g_cnt   [NNODES];
__device__ int g_rowptr[NNODES + 1];
__device__ int g_cursor[NNODES];
__device__ int g_esrc  [NEDGES];
__device__ int g_blksum[512];
__device__ int g_is64;

// packed f32x2 ops (PTX-only)
#define FMA_F32X2(d, a, b, c) \
    asm("fma.rn.f32x2 %0, %1, %2, %3;" : "=l"(d) : "l"(a), "l"(b), "l"(c))
#define ADD_F32X2(d, a, b) \
    asm("add.rn.f32x2 %0, %1, %2;" : "=l"(d) : "l"(a), "l"(b))
#define PACK2(d, s) \
    asm("mov.b64 %0, {%1, %1};" : "=l"(d) : "r"(__float_as_uint(s)))

// ---------------------------------------------------------------------------
__device__ __forceinline__ int edge_at(const int* ei, int idx, int E, int half) {
    if (g_is64) {
        const long long* ll = reinterpret_cast<const long long*>(ei);
        return (int)__ldg(ll + (size_t)half * E + idx);
    }
    return __ldg(ei + (size_t)half * E + idx);
}

__global__ void detect_kernel(const int* __restrict__ ei) {
    __shared__ int any_nonzero;
    if (threadIdx.x == 0) any_nonzero = 0;
    __syncthreads();
    int bad = 0;
    for (int w = 1 + 2 * threadIdx.x; w < 2048; w += 2 * blockDim.x)
        if (ei[w] != 0) bad = 1;
    if (bad) atomicOr(&any_nonzero, 1);
    __syncthreads();
    if (threadIdx.x == 0) g_is64 = (any_nonzero == 0) ? 1 : 0;
}

// ---------------------------------------------------------------------------
// CSR build
// ---------------------------------------------------------------------------
__global__ void zero_cnt_kernel() {
    int i = blockIdx.x * blockDim.x + threadIdx.x;
    if (i < NNODES) g_cnt[i] = 0;
}

__global__ void hist_kernel(const int* __restrict__ ei, int E) {
    int e = blockIdx.x * blockDim.x + threadIdx.x;
    if (e >= E) return;
    int d = edge_at(ei, e, E, 1);
    atomicAdd(&g_cnt[d], 1);
}

__global__ void scan1_kernel() {
    __shared__ int buf[2][256];
    int t = threadIdx.x, b = blockIdx.x;
    int i = b * 256 + t;
    int v = (i < NNODES) ? g_cnt[i] : 0;
    int cur = 0;
    buf[0][t] = v;
    __syncthreads();
#pragma unroll
    for (int off = 1; off < 256; off <<= 1) {
        int x = buf[cur][t];
        if (t >= off) x += buf[cur][t - off];
        buf[cur ^ 1][t] = x;
        cur ^= 1;
        __syncthreads();
    }
    int incl = buf[cur][t];
    if (i < NNODES) g_rowptr[i] = incl - v;
    if (t == 255) g_blksum[b] = incl;
}

__global__ void scan2_kernel() {
    __shared__ int buf[2][512];
    int t = threadIdx.x;
    int v = (t < NB_SCAN) ? g_blksum[t] : 0;
    int cur = 0;
    buf[0][t] = v;
    __syncthreads();
#pragma unroll
    for (int off = 1; off < 512; off <<= 1) {
        int x = buf[cur][t];
        if (t >= off) x += buf[cur][t - off];
        buf[cur ^ 1][t] = x;
        cur ^= 1;
        __syncthreads();
    }
    if (t < NB_SCAN) g_blksum[t] = buf[cur][t] - v;
}

__global__ void scan3_kernel() {
    int i = blockIdx.x * blockDim.x + threadIdx.x;
    if (i < NNODES) {
        int r = g_rowptr[i] + g_blksum[i >> 8];
        g_rowptr[i] = r;
        g_cursor[i] = r;
    }
    if (i == 0) g_rowptr[NNODES] = NEDGES;
}

__global__ void fill_kernel(const int* __restrict__ ei, int E) {
    int e = blockIdx.x * blockDim.x + threadIdx.x;
    if (e >= E) return;
    int s = edge_at(ei, e, E, 0);
    int d = edge_at(ei, e, E, 1);
    int pos = atomicAdd(&g_cursor[d], 1);
    g_esrc[pos] = s;
}

// ---------------------------------------------------------------------------
// 1) h1 = x @ W1 — warp = 16 rows; lane = (rg = lane>>3, kg = lane&7).
//    chunk = 32 k. Stage: (r4 = lane>>3, f8 = lane&7) LDG.128 covering whole
//    128B lines (amp 1); tile stride 40 floats -> conflict-free STS/LDS.128.
//    Register prefetch of next chunk overlaps DRAM latency with compute.
// ---------------------------------------------------------------------------
#define XT_STRIDE 40
__global__ void __launch_bounds__(128) gemm1_kernel(const float* __restrict__ x,
                                                    const float* __restrict__ W1) {
    __shared__ __align__(16) float Ws[8192];                 // W row-major [k][16]
    __shared__ __align__(16) float Xt[4][16 * XT_STRIDE];    // per-warp x tile

    int tid = threadIdx.x;
    for (int i = tid; i < 8192; i += 128)
        Ws[i] = W1[i];
    __syncthreads();

    int lane = tid & 31;
    int wrp  = tid >> 5;
    int gw   = blockIdx.x * 4 + wrp;
    int rbase = gw * 16;
    int r4 = lane >> 3;          // stage: which row (+4*it)   | compute: rg
    int f8 = lane & 7;           // stage: which float4 in line| compute: kg
    float* xt = Xt[wrp];

    const float4* xg = reinterpret_cast<const float4*>(x);

    // prefetch chunk 0: 4 LDG.128, each covering 4 full lines
    float4 R[4];
#pragma unroll
    for (int it = 0; it < 4; it++) {
        int grow = rbase + r4 + it * 4;
        if (grow >= NNODES) grow = NNODES - 1;
        R[it] = __ldg(xg + (size_t)grow * 128 + f8);
    }

    unsigned long long acc[32];     // [rr*8 + jp], rows rbase + rg*4 + rr
#pragma unroll
    for (int i = 0; i < 32; i++) acc[i] = 0ull;

#pragma unroll 1
    for (int kc = 0; kc < 16; kc++) {
        // store prefetched chunk into tile (conflict-free STS.128)
#pragma unroll
        for (int it = 0; it < 4; it++) {
            int r = r4 + it * 4;
            *reinterpret_cast<float4*>(&xt[r * XT_STRIDE + f8 * 4]) = R[it];
        }
        __syncwarp();

        // prefetch next chunk early (latency overlapped by compute below)
        if (kc + 1 < 16) {
#pragma unroll
            for (int it = 0; it < 4; it++) {
                int grow = rbase + r4 + it * 4;
                if (grow >= NNODES) grow = NNODES - 1;
                R[it] = __ldg(xg + (size_t)grow * 128 + (kc + 1) * 8 + f8);
            }
        }

        // compute: lane (rg=r4, kg=f8) handles rows rg*4..+3, k = kg*4..+3
#pragma unroll
        for (int rr = 0; rr < 4; rr++) {
            int r = r4 * 4 + rr;
            float4 xv = *reinterpret_cast<const float4*>(&xt[r * XT_STRIDE + f8 * 4]);
            float xvs[4] = {xv.x, xv.y, xv.z, xv.w};
#pragma unroll
            for (int d = 0; d < 4; d++) {
                int k = kc * 32 + f8 * 4 + d;
                const float4* wr = reinterpret_cast<const float4*>(&Ws[k * 16]);
                float4 w0 = wr[0], w1 = wr[1], w2 = wr[2], w3 = wr[3];
                unsigned long long wp[8];
                wp[0] = *reinterpret_cast<unsigned long long*>(&w0.x);
                wp[1] = *reinterpret_cast<unsigned long long*>(&w0.z);
                wp[2] = *reinterpret_cast<unsigned long long*>(&w1.x);
                wp[3] = *reinterpret_cast<unsigned long long*>(&w1.z);
                wp[4] = *reinterpret_cast<unsigned long long*>(&w2.x);
                wp[5] = *reinterpret_cast<unsigned long long*>(&w2.z);
                wp[6] = *reinterpret_cast<unsigned long long*>(&w3.x);
                wp[7] = *reinterpret_cast<unsigned long long*>(&w3.z);
                unsigned long long xx;
                PACK2(xx, xvs[d]);
#pragma unroll
                for (int jp = 0; jp < 8; jp++)
                    FMA_F32X2(acc[rr * 8 + jp], xx, wp[jp], acc[rr * 8 + jp]);
            }
        }
        __syncwarp();
    }

    // reduce over the 8 kg lanes (xor within 8-lane group)
#pragma unroll
    for (int off = 4; off >= 1; off >>= 1) {
#pragma unroll
        for (int i = 0; i < 32; i++) {
            unsigned long long o = __shfl_xor_sync(0xffffffffu, acc[i], off);
            ADD_F32X2(acc[i], acc[i], o);
        }
    }

    if (f8 == 0) {
#pragma unroll
        for (int rr = 0; rr < 4; rr++) {
            int row = rbase + r4 * 4 + rr;
            if (row < NNODES) {
                float4* o = reinterpret_cast<float4*>(g_h1 + (size_t)row * 16);
#pragma unroll
                for (int t = 0; t < 4; t++) {
                    float2 lo = *reinterpret_cast<float2*>(&acc[rr * 8 + t * 2]);
                    float2 hi = *reinterpret_cast<float2*>(&acc[rr * 8 + t * 2 + 1]);
                    o[t] = make_float4(lo.x, lo.y, hi.x, hi.y);
                }
            }
        }
    }
}

// ---------------------------------------------------------------------------
// 2/3) CSR aggregation, warp per node (writes EVERY node -> no pre-zero).
// ---------------------------------------------------------------------------
template <int LAYER>
__global__ void agg_kernel(const float* __restrict__ b1) {
    int warp = (blockIdx.x * blockDim.x + threadIdx.x) >> 5;
    if (warp >= NNODES) return;
    int lane = threadIdx.x & 31;
    int q = lane >> 3;
    int j = lane & 7;

    int start = __ldg(&g_rowptr[warp]);
    int end   = __ldg(&g_rowptr[warp + 1]);

    float4 bq;
    if (LAYER == 2) bq = __ldg(reinterpret_cast<const float4*>(b1) + q);

    float4 acc = make_float4(0.f, 0.f, 0.f, 0.f);
    const float4* feat = reinterpret_cast<const float4*>(
        (LAYER == 1) ? g_h1 : g_agg1);

    for (int e = start + j; e < end; e += 8) {
        int s = __ldg(&g_esrc[e]);
        float4 v = __ldg(feat + (size_t)s * 4 + q);
        if (LAYER == 2) {
            v.x = fmaxf(v.x + bq.x, 0.f);
            v.y = fmaxf(v.y + bq.y, 0.f);
            v.z = fmaxf(v.z + bq.z, 0.f);
            v.w = fmaxf(v.w + bq.w, 0.f);
        }
        acc.x += v.x; acc.y += v.y; acc.z += v.z; acc.w += v.w;
    }

#pragma unroll
    for (int off = 4; off >= 1; off >>= 1) {
        acc.x += __shfl_xor_sync(0xffffffffu, acc.x, off);
        acc.y += __shfl_xor_sync(0xffffffffu, acc.y, off);
        acc.z += __shfl_xor_sync(0xffffffffu, acc.z, off);
        acc.w += __shfl_xor_sync(0xffffffffu, acc.w, off);
    }

    if (j == 0) {
        float* dst = (LAYER == 1) ? g_agg1 : g_agg2;
        reinterpret_cast<float4*>(dst + (size_t)warp * 16)[q] = acc;
    }
}

// ---------------------------------------------------------------------------
// 4) out = log_softmax(g_agg2 @ W2 + b2)
// ---------------------------------------------------------------------------
__global__ void final_kernel(const float* __restrict__ W2,
                             const float* __restrict__ b2,
                             float* __restrict__ out) {
    int i = blockIdx.x * blockDim.x + threadIdx.x;
    if (i >= NNODES) return;

    float a[16];
    const float4* ap = reinterpret_cast<const float4*>(g_agg2 + (size_t)i * 16);
#pragma unroll
    for (int t = 0; t < 4; t++) {
        float4 v = ap[t];
        a[t * 4 + 0] = v.x; a[t * 4 + 1] = v.y;
        a[t * 4 + 2] = v.z; a[t * 4 + 3] = v.w;
    }

    float v[40];
#pragma unroll
    for (int j = 0; j < 40; j++) v[j] = __ldg(b2 + j);
#pragma unroll
    for (int k = 0; k < 16; k++) {
        float ak = a[k];
#pragma unroll
        for (int j = 0; j < 40; j++)
            v[j] = fmaf(ak, __ldg(W2 + k * 40 + j), v[j]);
    }

    float m = v[0];
#pragma unroll
    for (int j = 1; j < 40; j++) m = fmaxf(m, v[j]);
    float ssum = 0.f;
#pragma unroll
    for (int j = 0; j < 40; j++) ssum += expf(v[j] - m);
    float lse = m + logf(ssum);

    float4* op = reinterpret_cast<float4*>(out + (size_t)i * 40);
#pragma unroll
    for (int t = 0; t < 10; t++)
        op[t] = make_float4(v[t*4+0] - lse, v[t*4+1] - lse,
                            v[t*4+2] - lse, v[t*4+3] - lse);
}

// ---------------------------------------------------------------------------
extern "C" void kernel_launch(void* const* d_in, const int* in_sizes, int n_in,
                              void* d_out, int out_size) {
    const float* x  = nullptr;
    const int*   ei = nullptr;
    const float* W1 = nullptr;
    const float* b1 = nullptr;
    const float* W2 = nullptr;
    const float* b2 = nullptr;

    for (int i = 0; i < n_in; i++) {
        int sz = in_sizes[i];
        if      (sz == 51200000)                   x  = (const float*)d_in[i];
        else if (sz == 6400000 || sz == 12800000)  ei = (const int*)d_in[i];
        else if (sz == 8192)                       W1 = (const float*)d_in[i];
        else if (sz == 16)                         b1 = (const float*)d_in[i];
        else if (sz == 640)                        W2 = (const float*)d_in[i];
        else if (sz == 40)                         b2 = (const float*)d_in[i];
    }

    const int E = NEDGES;
    float* out = (float*)d_out;

    detect_kernel<<<1, 256>>>(ei);                            // 1
    zero_cnt_kernel<<<(NNODES + 255) / 256, 256>>>();         // 2
    hist_kernel<<<(E + 255) / 256, 256>>>(ei, E);             // 3
    gemm1_kernel<<<1563, 128>>>(x, W1);                       // 4  <- profiled
    scan1_kernel<<<NB_SCAN, 256>>>();                         // 5
    scan2_kernel<<<1, 512>>>();                               // 6
    scan3_kernel<<<(NNODES + 255) / 256, 256>>>();            // 7
    fill_kernel<<<(E + 255) / 256, 256>>>(ei, E);             // 8
    agg_kernel<1><<<(NNODES * 32 + 255) / 256, 256>>>(nullptr); // 9
    agg_kernel<2><<<(NNODES * 32 + 255) / 256, 256>>>(b1);    // 10
    final_kernel<<<(NNODES + 127) / 128, 128>>>(W2, b2, out); // 11
}

// round 14
// speedup vs baseline: 1.3659x; 1.3659x over previous
#include <cuda_runtime.h>
#include <cstdint>

// ---------------------------------------------------------------------------
// N=100000, 512 -> 16 -> 40, E=3.2M int32 edges.
// out = log_softmax( segsum(relu(segsum((xW1)[src])+b1)[src]) @ W2 + b2 )
// (W2 hoisted past the scatter by linearity of segment_sum.)
//
// R14: gemm1 = R10 verbatim (104us measured; R11-13 redesigns all regressed).
// Pipeline fat cut: prep merges zero+detect; scan2 removed (scan3 self-sums
// block offsets); relu+b1 applied once per node (h2) instead of per edge;
// agg gather unrolled x2 for MLP. 9 launches.
// RULE: __device__ globals only referenced in device code (ATS trap).
// ---------------------------------------------------------------------------

#define NNODES 100000
#define HID 16
#define NEDGES 3200000
#define NB_SCAN 391         // ceil(NNODES/256)

__device__ __align__(16) float g_h1 [NNODES * HID];   // x @ W1
__device__ __align__(16) float g_h2 [NNODES * HID];   // relu(segsum(h1)+b1)
__device__ __align__(16) float g_agg2[NNODES * HID];  // segsum(h2)
__device__ int g_cnt   [NNODES];
__device__ int g_rowptr[NNODES + 1];
__device__ int g_cursor[NNODES];
__device__ int g_esrc  [NEDGES];
__device__ int g_blksum[NB_SCAN];
__device__ int g_is64;

// packed f32x2 ops (PTX-only)
#define FMA_F32X2(d, a, b, c) \
    asm("fma.rn.f32x2 %0, %1, %2, %3;" : "=l"(d) : "l"(a), "l"(b), "l"(c))
#define ADD_F32X2(d, a, b) \
    asm("add.rn.f32x2 %0, %1, %2;" : "=l"(d) : "l"(a), "l"(b))
#define PACK2(d, s) \
    asm("mov.b64 %0, {%1, %1};" : "=l"(d) : "r"(__float_as_uint(s)))

// ---------------------------------------------------------------------------
__device__ __forceinline__ int edge_at(const int* ei, int idx, int E, int half) {
    if (g_is64) {
        const long long* ll = reinterpret_cast<const long long*>(ei);
        return (int)__ldg(ll + (size_t)half * E + idx);
    }
    return __ldg(ei + (size_t)half * E + idx);
}

// ---------------------------------------------------------------------------
// 1) prep: zero g_cnt (all blocks); block 0 additionally detects int64 storage
//    (int64 indices < 2^31 have all odd 32-bit words == 0).
// ---------------------------------------------------------------------------
__global__ void prep_kernel(const int* __restrict__ ei) {
    int i = blockIdx.x * blockDim.x + threadIdx.x;
    for (; i < NNODES; i += gridDim.x * blockDim.x) g_cnt[i] = 0;

    if (blockIdx.x == 0) {
        __shared__ int any_nonzero;
        if (threadIdx.x == 0) any_nonzero = 0;
        __syncthreads();
        int bad = 0;
        for (int w = 1 + 2 * threadIdx.x; w < 2048; w += 2 * blockDim.x)
            if (ei[w] != 0) bad = 1;
        if (bad) atomicOr(&any_nonzero, 1);
        __syncthreads();
        if (threadIdx.x == 0) g_is64 = (any_nonzero == 0) ? 1 : 0;
    }
}

// ---------------------------------------------------------------------------
// 2) histogram of destinations
// ---------------------------------------------------------------------------
__global__ void hist_kernel(const int* __restrict__ ei, int E) {
    int e = blockIdx.x * blockDim.x + threadIdx.x;
    if (e >= E) return;
    int d = edge_at(ei, e, E, 1);
    atomicAdd(&g_cnt[d], 1);
}

// ---------------------------------------------------------------------------
// 3) scan1: block-local exclusive scan; g_blksum[b] = block-inclusive total
// ---------------------------------------------------------------------------
__global__ void scan1_kernel() {
    __shared__ int buf[2][256];
    int t = threadIdx.x, b = blockIdx.x;
    int i = b * 256 + t;
    int v = (i < NNODES) ? g_cnt[i] : 0;
    int cur = 0;
    buf[0][t] = v;
    __syncthreads();
#pragma unroll
    for (int off = 1; off < 256; off <<= 1) {
        int x = buf[cur][t];
        if (t >= off) x += buf[cur][t - off];
        buf[cur ^ 1][t] = x;
        cur ^= 1;
        __syncthreads();
    }
    int incl = buf[cur][t];
    if (i < NNODES) g_rowptr[i] = incl - v;
    if (t == 255) g_blksum[b] = incl;
}

// ---------------------------------------------------------------------------
// 4) scan3: each block self-sums blksum[0..b-1] (<=390 ints), applies offset
// ---------------------------------------------------------------------------
__global__ void scan3_kernel() {
    __shared__ int sdata[256];
    int b = blockIdx.x, t = threadIdx.x;
    int s = 0;
    for (int i = t; i < b; i += 256) s += g_blksum[i];
    sdata[t] = s;
    __syncthreads();
#pragma unroll
    for (int off = 128; off >= 1; off >>= 1) {
        if (t < off) sdata[t] += sdata[t + off];
        __syncthreads();
    }
    int offset = sdata[0];
    int i = b * 256 + t;
    if (i < NNODES) {
        int r = g_rowptr[i] + offset;
        g_rowptr[i] = r;
        g_cursor[i] = r;
    }
    if (b == 0 && t == 0) g_rowptr[NNODES] = NEDGES;
}

// ---------------------------------------------------------------------------
// 5) fill CSR adjacency (src ids grouped by dst)
// ---------------------------------------------------------------------------
__global__ void fill_kernel(const int* __restrict__ ei, int E) {
    int e = blockIdx.x * blockDim.x + threadIdx.x;
    if (e >= E) return;
    int s = edge_at(ei, e, E, 0);
    int d = edge_at(ei, e, E, 1);
    int pos = atomicAdd(&g_cursor[d], 1);
    g_esrc[pos] = s;
}

// ---------------------------------------------------------------------------
// 6) h1 = x @ W1 — R10 verbatim (104us measured): warp=16 rows,
//    lane=(rg,kg), 4 rows/lane, 64k/kg-lane, FFMA2 col-pairs, padded W smem.
// ---------------------------------------------------------------------------
#define WS_STRIDE 1028
__global__ void __launch_bounds__(128) gemm1_kernel(const float* __restrict__ x,
                                                    const float* __restrict__ W1) {
    __shared__ __align__(16) float Ws[8 * WS_STRIDE];
    int tid = threadIdx.x;
    for (int i = tid; i < 8192; i += blockDim.x) {
        int k = i >> 4, j = i & 15;
        Ws[(k >> 6) * WS_STRIDE + (k & 63) * 16 + j] = W1[i];
    }
    __syncthreads();

    int lane = tid & 31;
    int wrp  = tid >> 5;
    int gw   = blockIdx.x * 4 + wrp;
    if (gw >= NNODES / 16) return;              // 6250 warps exactly
    int rg = lane >> 3;
    int kg = lane & 7;
    int row0 = gw * 16 + rg * 4;

    const float4* xv = reinterpret_cast<const float4*>(x);
    const float4* wsv = reinterpret_cast<const float4*>(Ws + kg * WS_STRIDE);

    unsigned long long acc[32];                 // [r*8 + jp]
#pragma unroll
    for (int i = 0; i < 32; i++) acc[i] = 0ull;

#pragma unroll
    for (int c = 0; c < 8; c++) {               // 8 chunks of 8 k
        float x8[4][8];
#pragma unroll
        for (int r = 0; r < 4; r++) {
            size_t base = (size_t)(row0 + r) * 128 + kg * 16 + c * 2;
            float4 a = __ldg(xv + base);
            float4 b = __ldg(xv + base + 1);
            x8[r][0]=a.x; x8[r][1]=a.y; x8[r][2]=a.z; x8[r][3]=a.w;
            x8[r][4]=b.x; x8[r][5]=b.y; x8[r][6]=b.z; x8[r][7]=b.w;
        }
#pragma unroll
        for (int ki = 0; ki < 8; ki++) {
            int kk = c * 8 + ki;
            float4 w0 = wsv[kk * 4 + 0];
            float4 w1 = wsv[kk * 4 + 1];
            float4 w2 = wsv[kk * 4 + 2];
            float4 w3 = wsv[kk * 4 + 3];
            unsigned long long wp[8];
            wp[0] = *reinterpret_cast<unsigned long long*>(&w0.x);
            wp[1] = *reinterpret_cast<unsigned long long*>(&w0.z);
            wp[2] = *reinterpret_cast<unsigned long long*>(&w1.x);
            wp[3] = *reinterpret_cast<unsigned long long*>(&w1.z);
            wp[4] = *reinterpret_cast<unsigned long long*>(&w2.x);
            wp[5] = *reinterpret_cast<unsigned long long*>(&w2.z);
            wp[6] = *reinterpret_cast<unsigned long long*>(&w3.x);
            wp[7] = *reinterpret_cast<unsigned long long*>(&w3.z);
#pragma unroll
            for (int r = 0; r < 4; r++) {
                unsigned long long xx;
                PACK2(xx, x8[r][ki]);
#pragma unroll
                for (int jp = 0; jp < 8; jp++)
                    FMA_F32X2(acc[r * 8 + jp], xx, wp[jp], acc[r * 8 + jp]);
            }
        }
    }

#pragma unroll
    for (int off = 4; off >= 1; off >>= 1) {
#pragma unroll
        for (int i = 0; i < 32; i++) {
            unsigned long long o = __shfl_xor_sync(0xffffffffu, acc[i], off);
            ADD_F32X2(acc[i], acc[i], o);
        }
    }

    if (kg == 0) {
#pragma unroll
        for (int r = 0; r < 4; r++) {
            float4* o = reinterpret_cast<float4*>(g_h1 + (size_t)(row0 + r) * 16);
#pragma unroll
            for (int t = 0; t < 4; t++) {
                float2 lo = *reinterpret_cast<float2*>(&acc[r * 8 + t * 2]);
                float2 hi = *reinterpret_cast<float2*>(&acc[r * 8 + t * 2 + 1]);
                o[t] = make_float4(lo.x, lo.y, hi.x, hi.y);
            }
        }
    }
}

// ---------------------------------------------------------------------------
// 7/8) CSR aggregation, warp per node, pure sums (relu+b1 applied once at the
//      LAYER 1 write). Gather unrolled x2 for memory-level parallelism.
// ---------------------------------------------------------------------------
template <int LAYER>
__global__ void agg_kernel(const float* __restrict__ b1) {
    int warp = (blockIdx.x * blockDim.x + threadIdx.x) >> 5;
    if (warp >= NNODES) return;
    int lane = threadIdx.x & 31;
    int q = lane >> 3;
    int j = lane & 7;

    int start = __ldg(&g_rowptr[warp]);
    int end   = __ldg(&g_rowptr[warp + 1]);

    const float4* feat = reinterpret_cast<const float4*>(
        (LAYER == 1) ? g_h1 : g_h2);

    float4 acc = make_float4(0.f, 0.f, 0.f, 0.f);
    int e = start + j;
    for (; e + 8 < end; e += 16) {
        int s0 = __ldg(&g_esrc[e]);
        int s1 = __ldg(&g_esrc[e + 8]);
        float4 v0 = __ldg(feat + (size_t)s0 * 4 + q);
        float4 v1 = __ldg(feat + (size_t)s1 * 4 + q);
        acc.x += v0.x + v1.x; acc.y += v0.y + v1.y;
        acc.z += v0.z + v1.z; acc.w += v0.w + v1.w;
    }
    if (e < end) {
        int s = __ldg(&g_esrc[e]);
        float4 v = __ldg(feat + (size_t)s * 4 + q);
        acc.x += v.x; acc.y += v.y; acc.z += v.z; acc.w += v.w;
    }

#pragma unroll
    for (int off = 4; off >= 1; off >>= 1) {
        acc.x += __shfl_xor_sync(0xffffffffu, acc.x, off);
        acc.y += __shfl_xor_sync(0xffffffffu, acc.y, off);
        acc.z += __shfl_xor_sync(0xffffffffu, acc.z, off);
        acc.w += __shfl_xor_sync(0xffffffffu, acc.w, off);
    }

    if (j == 0) {
        if (LAYER == 1) {
            float4 bq = __ldg(reinterpret_cast<const float4*>(b1) + q);
            acc.x = fmaxf(acc.x + bq.x, 0.f);
            acc.y = fmaxf(acc.y + bq.y, 0.f);
            acc.z = fmaxf(acc.z + bq.z, 0.f);
            acc.w = fmaxf(acc.w + bq.w, 0.f);
            reinterpret_cast<float4*>(g_h2 + (size_t)warp * 16)[q] = acc;
        } else {
            reinterpret_cast<float4*>(g_agg2 + (size_t)warp * 16)[q] = acc;
        }
    }
}

// ---------------------------------------------------------------------------
// 9) out = log_softmax(g_agg2 @ W2 + b2)
// ---------------------------------------------------------------------------
__global__ void final_kernel(const float* __restrict__ W2,
                             const float* __restrict__ b2,
                             float* __restrict__ out) {
    int i = blockIdx.x * blockDim.x + threadIdx.x;
    if (i >= NNODES) return;

    float a[16];
    const float4* ap = reinterpret_cast<const float4*>(g_agg2 + (size_t)i * 16);
#pragma unroll
    for (int t = 0; t < 4; t++) {
        float4 v = ap[t];
        a[t * 4 + 0] = v.x; a[t * 4 + 1] = v.y;
        a[t * 4 + 2] = v.z; a[t * 4 + 3] = v.w;
    }

    float v[40];
#pragma unroll
    for (int j = 0; j < 40; j++) v[j] = __ldg(b2 + j);
#pragma unroll
    for (int k = 0; k < 16; k++) {
        float ak = a[k];
#pragma unroll
        for (int j = 0; j < 40; j++)
            v[j] = fmaf(ak, __ldg(W2 + k * 40 + j), v[j]);
    }

    float m = v[0];
#pragma unroll
    for (int j = 1; j < 40; j++) m = fmaxf(m, v[j]);
    float ssum = 0.f;
#pragma unroll
    for (int j = 0; j < 40; j++) ssum += expf(v[j] - m);
    float lse = m + logf(ssum);

    float4* op = reinterpret_cast<float4*>(out + (size_t)i * 40);
#pragma unroll
    for (int t = 0; t < 10; t++)
        op[t] = make_float4(v[t*4+0] - lse, v[t*4+1] - lse,
                            v[t*4+2] - lse, v[t*4+3] - lse);
}

// ---------------------------------------------------------------------------
extern "C" void kernel_launch(void* const* d_in, const int* in_sizes, int n_in,
                              void* d_out, int out_size) {
    const float* x  = nullptr;
    const int*   ei = nullptr;
    const float* W1 = nullptr;
    const float* b1 = nullptr;
    const float* W2 = nullptr;
    const float* b2 = nullptr;

    for (int i = 0; i < n_in; i++) {
        int sz = in_sizes[i];
        if      (sz == 51200000)                   x  = (const float*)d_in[i];
        else if (sz == 6400000 || sz == 12800000)  ei = (const int*)d_in[i];
        else if (sz == 8192)                       W1 = (const float*)d_in[i];
        else if (sz == 16)                         b1 = (const float*)d_in[i];
        else if (sz == 640)                        W2 = (const float*)d_in[i];
        else if (sz == 40)                         b2 = (const float*)d_in[i];
    }

    const int E = NEDGES;
    float* out = (float*)d_out;

    prep_kernel<<<NB_SCAN, 256>>>(ei);                        // 1
    hist_kernel<<<(E + 255) / 256, 256>>>(ei, E);             // 2
    scan1_kernel<<<NB_SCAN, 256>>>();                         // 3
    scan3_kernel<<<NB_SCAN, 256>>>();                         // 4  <- profiled
    fill_kernel<<<(E + 255) / 256, 256>>>(ei, E);             // 5
    gemm1_kernel<<<1563, 128>>>(x, W1);                       // 6
    agg_kernel<1><<<(NNODES * 32 + 255) / 256, 256>>>(b1);    // 7
    agg_kernel<2><<<(NNODES * 32 + 255) / 256, 256>>>(nullptr); // 8
    final_kernel<<<(NNODES + 127) / 128, 128>>>(W2, b2, out); // 9
}